// round 14
// baseline (speedup 1.0000x reference)
#include <cuda_runtime.h>
#include <cuda_fp16.h>
#include <math.h>

#define NN 50000
#define EE 850000
#define F  128
#define HEADS 4
#define HIST_BLOCKS 512

// ---------------- scratch ----------------
__device__ __half g_hwh[NN * F];    // transformed features (fp16, gather operand)
__device__ __half g_feath[NN * F];  // layer output (fp16, next GEMM A operand)
__device__ float g_als[NN * HEADS];
__device__ float g_ald[NN * HEADS];
__device__ __half g_wh[2 * F * F];  // W1, W2 pre-converted to fp16
__device__ int   g_deg[NN];
__device__ int   g_off[NN + 1];
__device__ int   g_cur[NN];
__device__ int   g_ssrc[EE];

// ---------------- f32x2 helpers ----------------
__device__ __forceinline__ unsigned long long ffma2(unsigned long long a,
                                                    unsigned long long b,
                                                    unsigned long long c) {
    unsigned long long d;
    asm("fma.rn.f32x2 %0, %1, %2, %3;" : "=l"(d) : "l"(a), "l"(b), "l"(c));
    return d;
}
__device__ __forceinline__ unsigned long long dup2(float x) {
    unsigned long long d;
    asm("mov.b64 %0, {%1, %1};" : "=l"(d) : "f"(x));
    return d;
}

// ---------------- MMA helpers ----------------
__device__ __forceinline__ void ldsm_x4(unsigned* r, unsigned addr) {
    asm volatile("ldmatrix.sync.aligned.m8n8.x4.shared.b16 {%0,%1,%2,%3}, [%4];"
        : "=r"(r[0]), "=r"(r[1]), "=r"(r[2]), "=r"(r[3]) : "r"(addr));
}
__device__ __forceinline__ void mma16816(float* d, const unsigned* a,
                                         unsigned b0, unsigned b1) {
    asm volatile("mma.sync.aligned.m16n8k16.row.col.f32.f16.f16.f32 "
        "{%0,%1,%2,%3}, {%4,%5,%6,%7}, {%8,%9}, {%0,%1,%2,%3};"
        : "+f"(d[0]), "+f"(d[1]), "+f"(d[2]), "+f"(d[3])
        : "r"(a[0]), "r"(a[1]), "r"(a[2]), "r"(a[3]), "r"(b0), "r"(b1));
}

// ---------------- GEMM tile body ----------------
#define STRH 136
#define GEMM_SMEM (2 * 128 * STRH * 2)

__device__ __forceinline__ void gemm_tile(const float* __restrict__ Aext,
                                          const float* __restrict__ W,
                                          int wh_idx,
                                          const float* __restrict__ asrc,
                                          const float* __restrict__ adst,
                                          int n, int bx, char* smem) {
    __half* sA = (__half*)smem;
    __half* sW = (__half*)(smem + 128 * STRH * 2);
    int t = threadIdx.x;
    int n0 = bx * 128;
    const float4 zf4 = make_float4(0.f, 0.f, 0.f, 0.f);

    if (wh_idx < 0) {
        #pragma unroll
        for (int it = 0; it < 16; it++) {
            int idx = it * 256 + t;
            int row = idx >> 5;
            int c4 = (idx & 31) * 4;
            float4 v = (n0 + row < n) ? *(const float4*)(Aext + (size_t)(n0 + row) * F + c4) : zf4;
            __half2* da = (__half2*)(sA + row * STRH + c4);
            da[0] = __floats2half2_rn(v.x, v.y);
            da[1] = __floats2half2_rn(v.z, v.w);
            float4 w = *(const float4*)(W + (size_t)row * F + c4);
            __half2* dw = (__half2*)(sW + row * STRH + c4);
            dw[0] = __floats2half2_rn(w.x, w.y);
            dw[1] = __floats2half2_rn(w.z, w.w);
        }
    } else {
        const uint4 z16 = make_uint4(0u, 0u, 0u, 0u);
        #pragma unroll
        for (int it = 0; it < 8; it++) {
            int idx = it * 256 + t;
            int row = idx >> 4;
            int c8 = (idx & 15) * 8;
            uint4 v = (n0 + row < n) ? *(const uint4*)(g_feath + (size_t)(n0 + row) * F + c8) : z16;
            *(uint4*)(sA + row * STRH + c8) = v;
        }
        const __half* Wh = g_wh + wh_idx * (F * F);
        #pragma unroll
        for (int i = t; i < 2048; i += 256) {
            int row = i >> 4;
            int c8 = (i & 15) * 8;
            *(uint4*)(sW + row * STRH + c8) = *(const uint4*)(Wh + row * F + c8);
        }
    }
    __syncthreads();

    int wid = t >> 5, lane = t & 31;
    int M0 = wid * 16;

    float d[16][4];
    #pragma unroll
    for (int j = 0; j < 16; j++)
        #pragma unroll
        for (int q = 0; q < 4; q++) d[j][q] = 0.f;

    unsigned sAu = (unsigned)__cvta_generic_to_shared(sA);
    unsigned sWu = (unsigned)__cvta_generic_to_shared(sW);
    unsigned aBase = sAu + ((M0 + (lane & 15)) * STRH + (lane >> 4) * 8) * 2;
    unsigned bBase = sWu + (((lane & 7) + ((lane >> 4) & 1) * 8) * STRH
                            + ((lane >> 3) & 1) * 8) * 2;

    #pragma unroll
    for (int ks = 0; ks < 8; ks++) {
        unsigned a[4];
        ldsm_x4(a, aBase + ks * 32);
        #pragma unroll
        for (int g = 0; g < 8; g++) {
            unsigned b[4];
            ldsm_x4(b, bBase + g * (16 * STRH * 2) + ks * 32);
            mma16816(d[2 * g],     a, b[0], b[1]);
            mma16816(d[2 * g + 1], a, b[2], b[3]);
        }
    }

    int r0l = M0 + (lane >> 2);
    int grow0 = n0 + r0l, grow1 = grow0 + 8;
    int c2 = (lane & 3) * 2;
    bool v0 = grow0 < n, v1 = grow1 < n;

    float ps0[4] = {0, 0, 0, 0}, pd0[4] = {0, 0, 0, 0};
    float ps1[4] = {0, 0, 0, 0}, pd1[4] = {0, 0, 0, 0};
    #pragma unroll
    for (int j = 0; j < 16; j++) {
        const int head = j >> 2;
        float2 as = *(const float2*)(asrc + j * 8 + c2);
        float2 ad = *(const float2*)(adst + j * 8 + c2);
        ps0[head] += d[j][0] * as.x + d[j][1] * as.y;
        pd0[head] += d[j][0] * ad.x + d[j][1] * ad.y;
        ps1[head] += d[j][2] * as.x + d[j][3] * as.y;
        pd1[head] += d[j][2] * ad.x + d[j][3] * ad.y;
        if (v0) *(__half2*)(g_hwh + (size_t)grow0 * F + j * 8 + c2) =
            __floats2half2_rn(d[j][0], d[j][1]);
        if (v1) *(__half2*)(g_hwh + (size_t)grow1 * F + j * 8 + c2) =
            __floats2half2_rn(d[j][2], d[j][3]);
    }
    #pragma unroll
    for (int s = 1; s < 4; s <<= 1) {
        #pragma unroll
        for (int h = 0; h < 4; h++) {
            ps0[h] += __shfl_xor_sync(0xffffffffu, ps0[h], s);
            pd0[h] += __shfl_xor_sync(0xffffffffu, pd0[h], s);
            ps1[h] += __shfl_xor_sync(0xffffffffu, ps1[h], s);
            pd1[h] += __shfl_xor_sync(0xffffffffu, pd1[h], s);
        }
    }
    int h = lane & 3;
    float vs0 = (h == 0) ? ps0[0] : (h == 1) ? ps0[1] : (h == 2) ? ps0[2] : ps0[3];
    float vd0 = (h == 0) ? pd0[0] : (h == 1) ? pd0[1] : (h == 2) ? pd0[2] : pd0[3];
    float vs1 = (h == 0) ? ps1[0] : (h == 1) ? ps1[1] : (h == 2) ? ps1[2] : ps1[3];
    float vd1 = (h == 0) ? pd1[0] : (h == 1) ? pd1[1] : (h == 2) ? pd1[2] : pd1[3];
    if (v0) { g_als[grow0 * HEADS + h] = vs0; g_ald[grow0 * HEADS + h] = vd0; }
    if (v1) { g_als[grow1 * HEADS + h] = vs1; g_ald[grow1 * HEADS + h] = vd1; }
}

// ---------------- fused: gemm0 + hist + W1/W2 fp16 conversion ----------------
__global__ void __launch_bounds__(256)
fused0_kernel(const float* __restrict__ x,
              const float* __restrict__ W0,
              const float* __restrict__ asrc0,
              const float* __restrict__ adst0, int n,
              const int* __restrict__ dst, int e,
              const float* __restrict__ W1,
              const float* __restrict__ W2, int gemm_grid) {
    extern __shared__ char smem[];
    int bx = blockIdx.x;
    if (bx < gemm_grid) {
        gemm_tile(x, W0, -1, asrc0, adst0, n, bx, smem);
        return;
    }
    bx -= gemm_grid;
    if (bx < HIST_BLOCKS) {
        for (int i = bx * 256 + threadIdx.x; i < e; i += HIST_BLOCKS * 256)
            atomicAdd(&g_deg[dst[i]], 1);
        return;
    }
    bx -= HIST_BLOCKS;   // 0 or 1
    const float* Ws = bx ? W2 : W1;
    __half2* dh = (__half2*)(g_wh + bx * (F * F));
    for (int i = threadIdx.x; i < F * F / 2; i += 256) {
        float2 v = ((const float2*)Ws)[i];
        dh[i] = __floats2half2_rn(v.x, v.y);
    }
}

__global__ void __launch_bounds__(256)
gemm128_kernel(int wh_idx,
               const float* __restrict__ asrc,
               const float* __restrict__ adst, int n) {
    extern __shared__ char smem[];
    gemm_tile(nullptr, nullptr, wh_idx, asrc, adst, n, blockIdx.x, smem);
}

// ---------------- scan (re-zeroes g_deg) ----------------
__global__ void scan_kernel(int n) {
    __shared__ int wsum[32];
    __shared__ int s_total;
    int t = threadIdx.x, lane = t & 31, wid = t >> 5;
    int carry = 0;
    for (int base = 0; base < n; base += 1024) {
        int idx = base + t;
        int v = (idx < n) ? g_deg[idx] : 0;
        if (idx < n) g_deg[idx] = 0;
        int x = v;
        #pragma unroll
        for (int d = 1; d < 32; d <<= 1) {
            int y = __shfl_up_sync(0xffffffffu, x, d);
            if (lane >= d) x += y;
        }
        if (lane == 31) wsum[wid] = x;
        __syncthreads();
        if (wid == 0) {
            int w = wsum[lane];
            int xs = w;
            #pragma unroll
            for (int d = 1; d < 32; d <<= 1) {
                int y = __shfl_up_sync(0xffffffffu, xs, d);
                if (lane >= d) xs += y;
            }
            wsum[lane] = xs - w;
            if (lane == 31) s_total = xs;
        }
        __syncthreads();
        int excl = carry + wsum[wid] + (x - v);
        if (idx < n) { g_off[idx] = excl; g_cur[idx] = excl; }
        carry += s_total;
        __syncthreads();
    }
    if (t == 0) g_off[n] = carry;
}

__global__ void scatter_kernel(const int* __restrict__ src,
                               const int* __restrict__ dst, int e) {
    int i = blockIdx.x * blockDim.x + threadIdx.x;
    if (i < e) {
        int d = dst[i];
        int p = atomicAdd(&g_cur[d], 1);
        g_ssrc[p] = src[i];
    }
}

// ---------------- aggregation: head-major smem weights, fp16 gather ----------------
__global__ void __launch_bounds__(256, 6)
agg_kernel(const float* __restrict__ bias,
           float* __restrict__ outext, int use_ext,
           int apply_elu, int n) {
    __shared__ float s_wT[8][HEADS][32];   // [warp][head][edge]
    __shared__ int   s_sn[8][32];
    int wip = threadIdx.x >> 5;
    int node = blockIdx.x * 8 + wip;
    if (node >= n) return;
    int lane = threadIdx.x & 31;
    int hd = lane >> 3;
    int j0 = g_off[node], j1 = g_off[node + 1];
    float4 ald = *(const float4*)(g_ald + node * HEADS);
    float den = 0.f;
    unsigned long long acc01 = 0ULL, acc23 = 0ULL;

    const __half* hwl = g_hwh + lane * 4;            // per-lane feature base (4 halves = 8B)
    const float* whd = &s_wT[wip][hd][0];
    const int*   snp = &s_sn[wip][0];

    for (int base = j0; base < j1; base += 32) {
        int j = base + lane;
        float4 w4 = make_float4(0.f, 0.f, 0.f, 0.f);
        int sn = 0;
        if (j < j1) {
            sn = g_ssrc[j];
            float4 al = *(const float4*)(g_als + sn * HEADS);
            float e0 = al.x + ald.x; e0 = fmaxf(e0, 0.2f * e0);
            float e1 = al.y + ald.y; e1 = fmaxf(e1, 0.2f * e1);
            float e2 = al.z + ald.z; e2 = fmaxf(e2, 0.2f * e2);
            float e3 = al.w + ald.w; e3 = fmaxf(e3, 0.2f * e3);
            w4.x = __expf(e0); w4.y = __expf(e1);
            w4.z = __expf(e2); w4.w = __expf(e3);
        }
        s_sn[wip][lane] = sn;
        s_wT[wip][0][lane] = w4.x;
        s_wT[wip][1][lane] = w4.y;
        s_wT[wip][2][lane] = w4.z;
        s_wT[wip][3][lane] = w4.w;
        __syncwarp();
        int cnt = min(32, j1 - base);
        int ngrp = cnt >> 2;
        #pragma unroll 2
        for (int g = 0; g < ngrp; g++) {
            int4   s4 = *(const int4*)(snp + g * 4);
            float4 wv = *(const float4*)(whd + g * 4);
            {
                den += wv.x;
                unsigned long long w2 = dup2(wv.x);
                uint2 raw = *(const uint2*)(hwl + (size_t)s4.x * F);
                float2 f01 = __half22float2(*reinterpret_cast<__half2*>(&raw.x));
                float2 f23 = __half22float2(*reinterpret_cast<__half2*>(&raw.y));
                acc01 = ffma2(w2, *reinterpret_cast<unsigned long long*>(&f01), acc01);
                acc23 = ffma2(w2, *reinterpret_cast<unsigned long long*>(&f23), acc23);
            }
            {
                den += wv.y;
                unsigned long long w2 = dup2(wv.y);
                uint2 raw = *(const uint2*)(hwl + (size_t)s4.y * F);
                float2 f01 = __half22float2(*reinterpret_cast<__half2*>(&raw.x));
                float2 f23 = __half22float2(*reinterpret_cast<__half2*>(&raw.y));
                acc01 = ffma2(w2, *reinterpret_cast<unsigned long long*>(&f01), acc01);
                acc23 = ffma2(w2, *reinterpret_cast<unsigned long long*>(&f23), acc23);
            }
            {
                den += wv.z;
                unsigned long long w2 = dup2(wv.z);
                uint2 raw = *(const uint2*)(hwl + (size_t)s4.z * F);
                float2 f01 = __half22float2(*reinterpret_cast<__half2*>(&raw.x));
                float2 f23 = __half22float2(*reinterpret_cast<__half2*>(&raw.y));
                acc01 = ffma2(w2, *reinterpret_cast<unsigned long long*>(&f01), acc01);
                acc23 = ffma2(w2, *reinterpret_cast<unsigned long long*>(&f23), acc23);
            }
            {
                den += wv.w;
                unsigned long long w2 = dup2(wv.w);
                uint2 raw = *(const uint2*)(hwl + (size_t)s4.w * F);
                float2 f01 = __half22float2(*reinterpret_cast<__half2*>(&raw.x));
                float2 f23 = __half22float2(*reinterpret_cast<__half2*>(&raw.y));
                acc01 = ffma2(w2, *reinterpret_cast<unsigned long long*>(&f01), acc01);
                acc23 = ffma2(w2, *reinterpret_cast<unsigned long long*>(&f23), acc23);
            }
        }
        for (int jj = ngrp * 4; jj < cnt; jj++) {
            int s = snp[jj];
            float wgt = whd[jj];
            den += wgt;
            unsigned long long w2 = dup2(wgt);
            uint2 raw = *(const uint2*)(hwl + (size_t)s * F);
            float2 f01 = __half22float2(*reinterpret_cast<__half2*>(&raw.x));
            float2 f23 = __half22float2(*reinterpret_cast<__half2*>(&raw.y));
            acc01 = ffma2(w2, *reinterpret_cast<unsigned long long*>(&f01), acc01);
            acc23 = ffma2(w2, *reinterpret_cast<unsigned long long*>(&f23), acc23);
        }
        __syncwarp();
    }

    float2 a01 = *reinterpret_cast<float2*>(&acc01);
    float2 a23 = *reinterpret_cast<float2*>(&acc23);
    float inv = 1.f / (den + 1e-16f);
    float4 bv = *(const float4*)(bias + lane * 4);
    float4 o;
    o.x = fmaf(a01.x, inv, bv.x);
    o.y = fmaf(a01.y, inv, bv.y);
    o.z = fmaf(a23.x, inv, bv.z);
    o.w = fmaf(a23.y, inv, bv.w);
    if (apply_elu) {
        o.x = o.x > 0.f ? o.x : expm1f(o.x);
        o.y = o.y > 0.f ? o.y : expm1f(o.y);
        o.z = o.z > 0.f ? o.z : expm1f(o.z);
        o.w = o.w > 0.f ? o.w : expm1f(o.w);
    }
    if (use_ext) {
        *(float4*)(outext + (size_t)node * F + lane * 4) = o;
    } else {
        union { __half2 h[2]; uint2 u; } pk;
        pk.h[0] = __floats2half2_rn(o.x, o.y);
        pk.h[1] = __floats2half2_rn(o.z, o.w);
        *(uint2*)(g_feath + (size_t)node * F + lane * 4) = pk.u;
    }
}

// ---------------- launch ----------------
extern "C" void kernel_launch(void* const* d_in, const int* in_sizes, int n_in,
                              void* d_out, int out_size) {
    const float* x   = (const float*)d_in[0];
    const int*   src = (const int*)d_in[1];
    const int*   dst = (const int*)d_in[2];
    const int n = in_sizes[0] / F;
    const int e = in_sizes[1];

    const int gemm_grid = (n + 127) / 128;
    const int agg_grid  = (n + 7) / 8;

    cudaFuncSetAttribute(fused0_kernel,
                         cudaFuncAttributeMaxDynamicSharedMemorySize, GEMM_SMEM);
    cudaFuncSetAttribute(gemm128_kernel,
                         cudaFuncAttributeMaxDynamicSharedMemorySize, GEMM_SMEM);

    // 8 launches; agg0 is launch #4 -> ncu sample slot
    fused0_kernel<<<gemm_grid + HIST_BLOCKS + 2, 256, GEMM_SMEM>>>(
        x, (const float*)d_in[3], (const float*)d_in[4], (const float*)d_in[5],
        n, dst, e, (const float*)d_in[7], (const float*)d_in[11], gemm_grid);
    scan_kernel<<<1, 1024>>>(n);
    scatter_kernel<<<(e + 255) / 256, 256>>>(src, dst, e);
    agg_kernel<<<agg_grid, 256>>>((const float*)d_in[6], (float*)d_out, 0, 1, n);

    for (int l = 1; l < 3; l++) {
        const float* asrc = (const float*)d_in[4 + 4 * l];
        const float* adst = (const float*)d_in[5 + 4 * l];
        const float* b    = (const float*)d_in[6 + 4 * l];
        gemm128_kernel<<<gemm_grid, 256, GEMM_SMEM>>>(l - 1, asrc, adst, n);
        int last = (l == 2);
        agg_kernel<<<agg_grid, 256>>>(b, (float*)d_out, last, last ? 0 : 1, n);
    }
}

// round 15
// speedup vs baseline: 1.5367x; 1.5367x over previous
#include <cuda_runtime.h>
#include <cuda_fp16.h>
#include <math.h>

#define NN 50000
#define EE 850000
#define F  128
#define HEADS 4
#define HIST_BLOCKS 512

// ---------------- scratch ----------------
__device__ float  g_hw[NN * F];     // transformed features (fp32, gather operand; fits in L2)
__device__ __half g_feath[NN * F];  // layer output (fp16, next GEMM A operand)
__device__ float g_als[NN * HEADS];
__device__ float g_ald[NN * HEADS];
__device__ __half g_wh[2 * F * F];  // W1, W2 pre-converted to fp16
__device__ int   g_deg[NN];
__device__ int   g_off[NN + 1];
__device__ int   g_cur[NN];
__device__ int   g_ssrc[EE];

// ---------------- f32x2 helpers ----------------
__device__ __forceinline__ unsigned long long ffma2(unsigned long long a,
                                                    unsigned long long b,
                                                    unsigned long long c) {
    unsigned long long d;
    asm("fma.rn.f32x2 %0, %1, %2, %3;" : "=l"(d) : "l"(a), "l"(b), "l"(c));
    return d;
}
__device__ __forceinline__ unsigned long long dup2(float x) {
    unsigned long long d;
    asm("mov.b64 %0, {%1, %1};" : "=l"(d) : "f"(x));
    return d;
}

// ---------------- MMA helpers ----------------
__device__ __forceinline__ void ldsm_x4(unsigned* r, unsigned addr) {
    asm volatile("ldmatrix.sync.aligned.m8n8.x4.shared.b16 {%0,%1,%2,%3}, [%4];"
        : "=r"(r[0]), "=r"(r[1]), "=r"(r[2]), "=r"(r[3]) : "r"(addr));
}
__device__ __forceinline__ void mma16816(float* d, const unsigned* a,
                                         unsigned b0, unsigned b1) {
    asm volatile("mma.sync.aligned.m16n8k16.row.col.f32.f16.f16.f32 "
        "{%0,%1,%2,%3}, {%4,%5,%6,%7}, {%8,%9}, {%0,%1,%2,%3};"
        : "+f"(d[0]), "+f"(d[1]), "+f"(d[2]), "+f"(d[3])
        : "r"(a[0]), "r"(a[1]), "r"(a[2]), "r"(a[3]), "r"(b0), "r"(b1));
}

// ---------------- GEMM tile body ----------------
#define STRH 136
#define GEMM_SMEM (2 * 128 * STRH * 2)

__device__ __forceinline__ void gemm_tile(const float* __restrict__ Aext,
                                          const float* __restrict__ W,
                                          int wh_idx,
                                          const float* __restrict__ asrc,
                                          const float* __restrict__ adst,
                                          int n, int bx, char* smem) {
    __half* sA = (__half*)smem;
    __half* sW = (__half*)(smem + 128 * STRH * 2);
    int t = threadIdx.x;
    int n0 = bx * 128;
    const float4 zf4 = make_float4(0.f, 0.f, 0.f, 0.f);

    if (wh_idx < 0) {
        #pragma unroll
        for (int it = 0; it < 16; it++) {
            int idx = it * 256 + t;
            int row = idx >> 5;
            int c4 = (idx & 31) * 4;
            float4 v = (n0 + row < n) ? *(const float4*)(Aext + (size_t)(n0 + row) * F + c4) : zf4;
            __half2* da = (__half2*)(sA + row * STRH + c4);
            da[0] = __floats2half2_rn(v.x, v.y);
            da[1] = __floats2half2_rn(v.z, v.w);
            float4 w = *(const float4*)(W + (size_t)row * F + c4);
            __half2* dw = (__half2*)(sW + row * STRH + c4);
            dw[0] = __floats2half2_rn(w.x, w.y);
            dw[1] = __floats2half2_rn(w.z, w.w);
        }
    } else {
        const uint4 z16 = make_uint4(0u, 0u, 0u, 0u);
        #pragma unroll
        for (int it = 0; it < 8; it++) {
            int idx = it * 256 + t;
            int row = idx >> 4;
            int c8 = (idx & 15) * 8;
            uint4 v = (n0 + row < n) ? *(const uint4*)(g_feath + (size_t)(n0 + row) * F + c8) : z16;
            *(uint4*)(sA + row * STRH + c8) = v;
        }
        const __half* Wh = g_wh + wh_idx * (F * F);
        #pragma unroll
        for (int i = t; i < 2048; i += 256) {
            int row = i >> 4;
            int c8 = (i & 15) * 8;
            *(uint4*)(sW + row * STRH + c8) = *(const uint4*)(Wh + row * F + c8);
        }
    }
    __syncthreads();

    int wid = t >> 5, lane = t & 31;
    int M0 = wid * 16;

    float d[16][4];
    #pragma unroll
    for (int j = 0; j < 16; j++)
        #pragma unroll
        for (int q = 0; q < 4; q++) d[j][q] = 0.f;

    unsigned sAu = (unsigned)__cvta_generic_to_shared(sA);
    unsigned sWu = (unsigned)__cvta_generic_to_shared(sW);
    unsigned aBase = sAu + ((M0 + (lane & 15)) * STRH + (lane >> 4) * 8) * 2;
    unsigned bBase = sWu + (((lane & 7) + ((lane >> 4) & 1) * 8) * STRH
                            + ((lane >> 3) & 1) * 8) * 2;

    #pragma unroll
    for (int ks = 0; ks < 8; ks++) {
        unsigned a[4];
        ldsm_x4(a, aBase + ks * 32);
        #pragma unroll
        for (int g = 0; g < 8; g++) {
            unsigned b[4];
            ldsm_x4(b, bBase + g * (16 * STRH * 2) + ks * 32);
            mma16816(d[2 * g],     a, b[0], b[1]);
            mma16816(d[2 * g + 1], a, b[2], b[3]);
        }
    }

    int r0l = M0 + (lane >> 2);
    int grow0 = n0 + r0l, grow1 = grow0 + 8;
    int c2 = (lane & 3) * 2;
    bool v0 = grow0 < n, v1 = grow1 < n;

    float ps0[4] = {0, 0, 0, 0}, pd0[4] = {0, 0, 0, 0};
    float ps1[4] = {0, 0, 0, 0}, pd1[4] = {0, 0, 0, 0};
    #pragma unroll
    for (int j = 0; j < 16; j++) {
        const int head = j >> 2;
        float2 as = *(const float2*)(asrc + j * 8 + c2);
        float2 ad = *(const float2*)(adst + j * 8 + c2);
        ps0[head] += d[j][0] * as.x + d[j][1] * as.y;
        pd0[head] += d[j][0] * ad.x + d[j][1] * ad.y;
        ps1[head] += d[j][2] * as.x + d[j][3] * as.y;
        pd1[head] += d[j][2] * ad.x + d[j][3] * ad.y;
        if (v0) *(float2*)(g_hw + (size_t)grow0 * F + j * 8 + c2) = make_float2(d[j][0], d[j][1]);
        if (v1) *(float2*)(g_hw + (size_t)grow1 * F + j * 8 + c2) = make_float2(d[j][2], d[j][3]);
    }
    #pragma unroll
    for (int s = 1; s < 4; s <<= 1) {
        #pragma unroll
        for (int h = 0; h < 4; h++) {
            ps0[h] += __shfl_xor_sync(0xffffffffu, ps0[h], s);
            pd0[h] += __shfl_xor_sync(0xffffffffu, pd0[h], s);
            ps1[h] += __shfl_xor_sync(0xffffffffu, ps1[h], s);
            pd1[h] += __shfl_xor_sync(0xffffffffu, pd1[h], s);
        }
    }
    int h = lane & 3;
    float vs0 = (h == 0) ? ps0[0] : (h == 1) ? ps0[1] : (h == 2) ? ps0[2] : ps0[3];
    float vd0 = (h == 0) ? pd0[0] : (h == 1) ? pd0[1] : (h == 2) ? pd0[2] : pd0[3];
    float vs1 = (h == 0) ? ps1[0] : (h == 1) ? ps1[1] : (h == 2) ? ps1[2] : ps1[3];
    float vd1 = (h == 0) ? pd1[0] : (h == 1) ? pd1[1] : (h == 2) ? pd1[2] : pd1[3];
    if (v0) { g_als[grow0 * HEADS + h] = vs0; g_ald[grow0 * HEADS + h] = vd0; }
    if (v1) { g_als[grow1 * HEADS + h] = vs1; g_ald[grow1 * HEADS + h] = vd1; }
}

// ---------------- fused: gemm0 + hist + W1/W2 fp16 conversion ----------------
__global__ void __launch_bounds__(256)
fused0_kernel(const float* __restrict__ x,
              const float* __restrict__ W0,
              const float* __restrict__ asrc0,
              const float* __restrict__ adst0, int n,
              const int* __restrict__ dst, int e,
              const float* __restrict__ W1,
              const float* __restrict__ W2, int gemm_grid) {
    extern __shared__ char smem[];
    int bx = blockIdx.x;
    if (bx < gemm_grid) {
        gemm_tile(x, W0, -1, asrc0, adst0, n, bx, smem);
        return;
    }
    bx -= gemm_grid;
    if (bx < HIST_BLOCKS) {
        for (int i = bx * 256 + threadIdx.x; i < e; i += HIST_BLOCKS * 256)
            atomicAdd(&g_deg[dst[i]], 1);
        return;
    }
    bx -= HIST_BLOCKS;   // 0 or 1
    const float* Ws = bx ? W2 : W1;
    __half2* dh = (__half2*)(g_wh + bx * (F * F));
    for (int i = threadIdx.x; i < F * F / 2; i += 256) {
        float2 v = ((const float2*)Ws)[i];
        dh[i] = __floats2half2_rn(v.x, v.y);
    }
}

__global__ void __launch_bounds__(256)
gemm128_kernel(int wh_idx,
               const float* __restrict__ asrc,
               const float* __restrict__ adst, int n) {
    extern __shared__ char smem[];
    gemm_tile(nullptr, nullptr, wh_idx, asrc, adst, n, blockIdx.x, smem);
}

// ---------------- scan: software-pipelined (prefetch next chunk), re-zeroes g_deg ----------------
__global__ void scan_kernel(int n) {
    __shared__ int wsum[32];
    __shared__ int s_total;
    int t = threadIdx.x, lane = t & 31, wid = t >> 5;
    int carry = 0;
    int v_next = (t < n) ? g_deg[t] : 0;     // prefetch chunk 0
    for (int base = 0; base < n; base += 1024) {
        int idx = base + t;
        int v = v_next;
        // prefetch next chunk before any barriers (hides L2/DRAM latency)
        int nidx = idx + 1024;
        if (base + 1024 < n)
            v_next = (nidx < n) ? g_deg[nidx] : 0;
        if (idx < n) g_deg[idx] = 0;
        int x = v;
        #pragma unroll
        for (int d = 1; d < 32; d <<= 1) {
            int y = __shfl_up_sync(0xffffffffu, x, d);
            if (lane >= d) x += y;
        }
        if (lane == 31) wsum[wid] = x;
        __syncthreads();
        if (wid == 0) {
            int w = wsum[lane];
            int xs = w;
            #pragma unroll
            for (int d = 1; d < 32; d <<= 1) {
                int y = __shfl_up_sync(0xffffffffu, xs, d);
                if (lane >= d) xs += y;
            }
            wsum[lane] = xs - w;
            if (lane == 31) s_total = xs;
        }
        __syncthreads();
        int excl = carry + wsum[wid] + (x - v);
        if (idx < n) { g_off[idx] = excl; g_cur[idx] = excl; }
        carry += s_total;
        __syncthreads();
    }
    if (t == 0) g_off[n] = carry;
}

__global__ void scatter_kernel(const int* __restrict__ src,
                               const int* __restrict__ dst, int e) {
    int i = blockIdx.x * blockDim.x + threadIdx.x;
    if (i < e) {
        int d = dst[i];
        int p = atomicAdd(&g_cur[d], 1);
        g_ssrc[p] = src[i];
    }
}

// ---------------- aggregation: R13 fp32 path (LTS-floor bound) ----------------
__global__ void __launch_bounds__(256, 6)
agg_kernel(const float* __restrict__ bias,
           float* __restrict__ outext, int use_ext,
           int apply_elu, int n) {
    __shared__ float s_wT[8][HEADS][32];   // [warp][head][edge]
    __shared__ int   s_sn[8][32];
    int wip = threadIdx.x >> 5;
    int node = blockIdx.x * 8 + wip;
    if (node >= n) return;
    int lane = threadIdx.x & 31;
    int hd = lane >> 3;
    int j0 = g_off[node], j1 = g_off[node + 1];
    float4 ald = *(const float4*)(g_ald + node * HEADS);
    float den = 0.f;
    unsigned long long acc01 = 0ULL, acc23 = 0ULL;

    const float* hwl = g_hw + lane * 4;
    const float* whd = &s_wT[wip][hd][0];
    const int*   snp = &s_sn[wip][0];

    for (int base = j0; base < j1; base += 32) {
        int j = base + lane;
        float4 w4 = make_float4(0.f, 0.f, 0.f, 0.f);
        int sn = 0;
        if (j < j1) {
            sn = g_ssrc[j];
            float4 al = *(const float4*)(g_als + sn * HEADS);
            float e0 = al.x + ald.x; e0 = fmaxf(e0, 0.2f * e0);
            float e1 = al.y + ald.y; e1 = fmaxf(e1, 0.2f * e1);
            float e2 = al.z + ald.z; e2 = fmaxf(e2, 0.2f * e2);
            float e3 = al.w + ald.w; e3 = fmaxf(e3, 0.2f * e3);
            w4.x = __expf(e0); w4.y = __expf(e1);
            w4.z = __expf(e2); w4.w = __expf(e3);
        }
        s_sn[wip][lane] = sn;
        s_wT[wip][0][lane] = w4.x;
        s_wT[wip][1][lane] = w4.y;
        s_wT[wip][2][lane] = w4.z;
        s_wT[wip][3][lane] = w4.w;
        __syncwarp();
        int cnt = min(32, j1 - base);
        int ngrp = cnt >> 2;
        #pragma unroll 2
        for (int g = 0; g < ngrp; g++) {
            int4   s4 = *(const int4*)(snp + g * 4);
            float4 wv = *(const float4*)(whd + g * 4);
            {
                den += wv.x;
                unsigned long long w2 = dup2(wv.x);
                float4 hv = *(const float4*)(hwl + (size_t)s4.x * F);
                const unsigned long long* hq = reinterpret_cast<const unsigned long long*>(&hv);
                acc01 = ffma2(w2, hq[0], acc01);
                acc23 = ffma2(w2, hq[1], acc23);
            }
            {
                den += wv.y;
                unsigned long long w2 = dup2(wv.y);
                float4 hv = *(const float4*)(hwl + (size_t)s4.y * F);
                const unsigned long long* hq = reinterpret_cast<const unsigned long long*>(&hv);
                acc01 = ffma2(w2, hq[0], acc01);
                acc23 = ffma2(w2, hq[1], acc23);
            }
            {
                den += wv.z;
                unsigned long long w2 = dup2(wv.z);
                float4 hv = *(const float4*)(hwl + (size_t)s4.z * F);
                const unsigned long long* hq = reinterpret_cast<const unsigned long long*>(&hv);
                acc01 = ffma2(w2, hq[0], acc01);
                acc23 = ffma2(w2, hq[1], acc23);
            }
            {
                den += wv.w;
                unsigned long long w2 = dup2(wv.w);
                float4 hv = *(const float4*)(hwl + (size_t)s4.w * F);
                const unsigned long long* hq = reinterpret_cast<const unsigned long long*>(&hv);
                acc01 = ffma2(w2, hq[0], acc01);
                acc23 = ffma2(w2, hq[1], acc23);
            }
        }
        for (int jj = ngrp * 4; jj < cnt; jj++) {
            int s = snp[jj];
            float wgt = whd[jj];
            den += wgt;
            unsigned long long w2 = dup2(wgt);
            float4 hv = *(const float4*)(hwl + (size_t)s * F);
            const unsigned long long* hq = reinterpret_cast<const unsigned long long*>(&hv);
            acc01 = ffma2(w2, hq[0], acc01);
            acc23 = ffma2(w2, hq[1], acc23);
        }
        __syncwarp();
    }

    float2 a01 = *reinterpret_cast<float2*>(&acc01);
    float2 a23 = *reinterpret_cast<float2*>(&acc23);
    float inv = 1.f / (den + 1e-16f);
    float4 bv = *(const float4*)(bias + lane * 4);
    float4 o;
    o.x = fmaf(a01.x, inv, bv.x);
    o.y = fmaf(a01.y, inv, bv.y);
    o.z = fmaf(a23.x, inv, bv.z);
    o.w = fmaf(a23.y, inv, bv.w);
    if (apply_elu) {
        o.x = o.x > 0.f ? o.x : expm1f(o.x);
        o.y = o.y > 0.f ? o.y : expm1f(o.y);
        o.z = o.z > 0.f ? o.z : expm1f(o.z);
        o.w = o.w > 0.f ? o.w : expm1f(o.w);
    }
    if (use_ext) {
        *(float4*)(outext + (size_t)node * F + lane * 4) = o;
    } else {
        union { __half2 h[2]; uint2 u; } pk;
        pk.h[0] = __floats2half2_rn(o.x, o.y);
        pk.h[1] = __floats2half2_rn(o.z, o.w);
        *(uint2*)(g_feath + (size_t)node * F + lane * 4) = pk.u;
    }
}

// ---------------- launch ----------------
extern "C" void kernel_launch(void* const* d_in, const int* in_sizes, int n_in,
                              void* d_out, int out_size) {
    const float* x   = (const float*)d_in[0];
    const int*   src = (const int*)d_in[1];
    const int*   dst = (const int*)d_in[2];
    const int n = in_sizes[0] / F;
    const int e = in_sizes[1];

    const int gemm_grid = (n + 127) / 128;
    const int agg_grid  = (n + 7) / 8;

    cudaFuncSetAttribute(fused0_kernel,
                         cudaFuncAttributeMaxDynamicSharedMemorySize, GEMM_SMEM);
    cudaFuncSetAttribute(gemm128_kernel,
                         cudaFuncAttributeMaxDynamicSharedMemorySize, GEMM_SMEM);

    // 8 launches; agg0 is launch #4 -> ncu sample slot
    fused0_kernel<<<gemm_grid + HIST_BLOCKS + 2, 256, GEMM_SMEM>>>(
        x, (const float*)d_in[3], (const float*)d_in[4], (const float*)d_in[5],
        n, dst, e, (const float*)d_in[7], (const float*)d_in[11], gemm_grid);
    scan_kernel<<<1, 1024>>>(n);
    scatter_kernel<<<(e + 255) / 256, 256>>>(src, dst, e);
    agg_kernel<<<agg_grid, 256>>>((const float*)d_in[6], (float*)d_out, 0, 1, n);

    for (int l = 1; l < 3; l++) {
        const float* asrc = (const float*)d_in[4 + 4 * l];
        const float* adst = (const float*)d_in[5 + 4 * l];
        const float* b    = (const float*)d_in[6 + 4 * l];
        gemm128_kernel<<<gemm_grid, 256, GEMM_SMEM>>>(l - 1, asrc, adst, n);
        int last = (l == 2);
        agg_kernel<<<agg_grid, 256>>>(b, (float*)d_out, last, last ? 0 : 1, n);
    }
}

// round 16
// speedup vs baseline: 1.5533x; 1.0108x over previous
#include <cuda_runtime.h>
#include <cuda_fp16.h>
#include <math.h>

#define NN 50000
#define EE 850000
#define F  128
#define HEADS 4
#define HIST_BLOCKS 512

// ---------------- scratch ----------------
__device__ float  g_hw[NN * F];     // transformed features (fp32, gather operand; fits in L2)
__device__ __half g_feath[NN * F];  // layer output (fp16, next GEMM A operand)
__device__ float g_als[NN * HEADS];
__device__ float g_ald[NN * HEADS];
__device__ __half g_wh[2 * F * F];  // W1, W2 pre-converted to fp16
__device__ int   g_deg[NN];
__device__ int   g_off[NN + 1];
__device__ int   g_cur[NN];
__device__ int   g_ssrc[EE];

// ---------------- f32x2 helpers ----------------
__device__ __forceinline__ unsigned long long ffma2(unsigned long long a,
                                                    unsigned long long b,
                                                    unsigned long long c) {
    unsigned long long d;
    asm("fma.rn.f32x2 %0, %1, %2, %3;" : "=l"(d) : "l"(a), "l"(b), "l"(c));
    return d;
}
__device__ __forceinline__ unsigned long long dup2(float x) {
    unsigned long long d;
    asm("mov.b64 %0, {%1, %1};" : "=l"(d) : "f"(x));
    return d;
}

// ---------------- MMA helpers ----------------
__device__ __forceinline__ void ldsm_x4(unsigned* r, unsigned addr) {
    asm volatile("ldmatrix.sync.aligned.m8n8.x4.shared.b16 {%0,%1,%2,%3}, [%4];"
        : "=r"(r[0]), "=r"(r[1]), "=r"(r[2]), "=r"(r[3]) : "r"(addr));
}
__device__ __forceinline__ void mma16816(float* d, const unsigned* a,
                                         unsigned b0, unsigned b1) {
    asm volatile("mma.sync.aligned.m16n8k16.row.col.f32.f16.f16.f32 "
        "{%0,%1,%2,%3}, {%4,%5,%6,%7}, {%8,%9}, {%0,%1,%2,%3};"
        : "+f"(d[0]), "+f"(d[1]), "+f"(d[2]), "+f"(d[3])
        : "r"(a[0]), "r"(a[1]), "r"(a[2]), "r"(a[3]), "r"(b0), "r"(b1));
}

// ---------------- GEMM tile body ----------------
#define STRH 136
#define GEMM_SMEM (2 * 128 * STRH * 2)

__device__ __forceinline__ void gemm_tile(const float* __restrict__ Aext,
                                          const float* __restrict__ W,
                                          int wh_idx,
                                          const float* __restrict__ asrc,
                                          const float* __restrict__ adst,
                                          int n, int bx, char* smem) {
    __half* sA = (__half*)smem;
    __half* sW = (__half*)(smem + 128 * STRH * 2);
    int t = threadIdx.x;
    int n0 = bx * 128;
    const float4 zf4 = make_float4(0.f, 0.f, 0.f, 0.f);

    if (wh_idx < 0) {
        #pragma unroll
        for (int it = 0; it < 16; it++) {
            int idx = it * 256 + t;
            int row = idx >> 5;
            int c4 = (idx & 31) * 4;
            float4 v = (n0 + row < n) ? *(const float4*)(Aext + (size_t)(n0 + row) * F + c4) : zf4;
            __half2* da = (__half2*)(sA + row * STRH + c4);
            da[0] = __floats2half2_rn(v.x, v.y);
            da[1] = __floats2half2_rn(v.z, v.w);
            float4 w = *(const float4*)(W + (size_t)row * F + c4);
            __half2* dw = (__half2*)(sW + row * STRH + c4);
            dw[0] = __floats2half2_rn(w.x, w.y);
            dw[1] = __floats2half2_rn(w.z, w.w);
        }
    } else {
        const uint4 z16 = make_uint4(0u, 0u, 0u, 0u);
        #pragma unroll
        for (int it = 0; it < 8; it++) {
            int idx = it * 256 + t;
            int row = idx >> 4;
            int c8 = (idx & 15) * 8;
            uint4 v = (n0 + row < n) ? *(const uint4*)(g_feath + (size_t)(n0 + row) * F + c8) : z16;
            *(uint4*)(sA + row * STRH + c8) = v;
        }
        const __half* Wh = g_wh + wh_idx * (F * F);
        #pragma unroll
        for (int i = t; i < 2048; i += 256) {
            int row = i >> 4;
            int c8 = (i & 15) * 8;
            *(uint4*)(sW + row * STRH + c8) = *(const uint4*)(Wh + row * F + c8);
        }
    }
    __syncthreads();

    int wid = t >> 5, lane = t & 31;
    int M0 = wid * 16;

    float d[16][4];
    #pragma unroll
    for (int j = 0; j < 16; j++)
        #pragma unroll
        for (int q = 0; q < 4; q++) d[j][q] = 0.f;

    unsigned sAu = (unsigned)__cvta_generic_to_shared(sA);
    unsigned sWu = (unsigned)__cvta_generic_to_shared(sW);
    unsigned aBase = sAu + ((M0 + (lane & 15)) * STRH + (lane >> 4) * 8) * 2;
    unsigned bBase = sWu + (((lane & 7) + ((lane >> 4) & 1) * 8) * STRH
                            + ((lane >> 3) & 1) * 8) * 2;

    #pragma unroll
    for (int ks = 0; ks < 8; ks++) {
        unsigned a[4];
        ldsm_x4(a, aBase + ks * 32);
        #pragma unroll
        for (int g = 0; g < 8; g++) {
            unsigned b[4];
            ldsm_x4(b, bBase + g * (16 * STRH * 2) + ks * 32);
            mma16816(d[2 * g],     a, b[0], b[1]);
            mma16816(d[2 * g + 1], a, b[2], b[3]);
        }
    }

    int r0l = M0 + (lane >> 2);
    int grow0 = n0 + r0l, grow1 = grow0 + 8;
    int c2 = (lane & 3) * 2;
    bool v0 = grow0 < n, v1 = grow1 < n;

    float ps0[4] = {0, 0, 0, 0}, pd0[4] = {0, 0, 0, 0};
    float ps1[4] = {0, 0, 0, 0}, pd1[4] = {0, 0, 0, 0};
    #pragma unroll
    for (int j = 0; j < 16; j++) {
        const int head = j >> 2;
        float2 as = *(const float2*)(asrc + j * 8 + c2);
        float2 ad = *(const float2*)(adst + j * 8 + c2);
        ps0[head] += d[j][0] * as.x + d[j][1] * as.y;
        pd0[head] += d[j][0] * ad.x + d[j][1] * ad.y;
        ps1[head] += d[j][2] * as.x + d[j][3] * as.y;
        pd1[head] += d[j][2] * ad.x + d[j][3] * ad.y;
        if (v0) *(float2*)(g_hw + (size_t)grow0 * F + j * 8 + c2) = make_float2(d[j][0], d[j][1]);
        if (v1) *(float2*)(g_hw + (size_t)grow1 * F + j * 8 + c2) = make_float2(d[j][2], d[j][3]);
    }
    #pragma unroll
    for (int s = 1; s < 4; s <<= 1) {
        #pragma unroll
        for (int h = 0; h < 4; h++) {
            ps0[h] += __shfl_xor_sync(0xffffffffu, ps0[h], s);
            pd0[h] += __shfl_xor_sync(0xffffffffu, pd0[h], s);
            ps1[h] += __shfl_xor_sync(0xffffffffu, ps1[h], s);
            pd1[h] += __shfl_xor_sync(0xffffffffu, pd1[h], s);
        }
    }
    int h = lane & 3;
    float vs0 = (h == 0) ? ps0[0] : (h == 1) ? ps0[1] : (h == 2) ? ps0[2] : ps0[3];
    float vd0 = (h == 0) ? pd0[0] : (h == 1) ? pd0[1] : (h == 2) ? pd0[2] : pd0[3];
    float vs1 = (h == 0) ? ps1[0] : (h == 1) ? ps1[1] : (h == 2) ? ps1[2] : ps1[3];
    float vd1 = (h == 0) ? pd1[0] : (h == 1) ? pd1[1] : (h == 2) ? pd1[2] : pd1[3];
    if (v0) { g_als[grow0 * HEADS + h] = vs0; g_ald[grow0 * HEADS + h] = vd0; }
    if (v1) { g_als[grow1 * HEADS + h] = vs1; g_ald[grow1 * HEADS + h] = vd1; }
}

// ---------------- fused: gemm0 + hist + W1/W2 fp16 conversion ----------------
__global__ void __launch_bounds__(256)
fused0_kernel(const float* __restrict__ x,
              const float* __restrict__ W0,
              const float* __restrict__ asrc0,
              const float* __restrict__ adst0, int n,
              const int* __restrict__ dst, int e,
              const float* __restrict__ W1,
              const float* __restrict__ W2, int gemm_grid) {
    extern __shared__ char smem[];
    int bx = blockIdx.x;
    if (bx < gemm_grid) {
        gemm_tile(x, W0, -1, asrc0, adst0, n, bx, smem);
        return;
    }
    bx -= gemm_grid;
    if (bx < HIST_BLOCKS) {
        for (int i = bx * 256 + threadIdx.x; i < e; i += HIST_BLOCKS * 256)
            atomicAdd(&g_deg[dst[i]], 1);
        return;
    }
    bx -= HIST_BLOCKS;   // 0 or 1
    const float* Ws = bx ? W2 : W1;
    __half2* dh = (__half2*)(g_wh + bx * (F * F));
    for (int i = threadIdx.x; i < F * F / 2; i += 256) {
        float2 v = ((const float2*)Ws)[i];
        dh[i] = __floats2half2_rn(v.x, v.y);
    }
}

__global__ void __launch_bounds__(256)
gemm128_kernel(int wh_idx,
               const float* __restrict__ asrc,
               const float* __restrict__ adst, int n) {
    extern __shared__ char smem[];
    gemm_tile(nullptr, nullptr, wh_idx, asrc, adst, n, blockIdx.x, smem);
}

// ---------------- scan: software-pipelined, re-zeroes g_deg ----------------
__global__ void scan_kernel(int n) {
    __shared__ int wsum[32];
    __shared__ int s_total;
    int t = threadIdx.x, lane = t & 31, wid = t >> 5;
    int carry = 0;
    int v_next = (t < n) ? g_deg[t] : 0;
    for (int base = 0; base < n; base += 1024) {
        int idx = base + t;
        int v = v_next;
        int nidx = idx + 1024;
        if (base + 1024 < n)
            v_next = (nidx < n) ? g_deg[nidx] : 0;
        if (idx < n) g_deg[idx] = 0;
        int x = v;
        #pragma unroll
        for (int d = 1; d < 32; d <<= 1) {
            int y = __shfl_up_sync(0xffffffffu, x, d);
            if (lane >= d) x += y;
        }
        if (lane == 31) wsum[wid] = x;
        __syncthreads();
        if (wid == 0) {
            int w = wsum[lane];
            int xs = w;
            #pragma unroll
            for (int d = 1; d < 32; d <<= 1) {
                int y = __shfl_up_sync(0xffffffffu, xs, d);
                if (lane >= d) xs += y;
            }
            wsum[lane] = xs - w;
            if (lane == 31) s_total = xs;
        }
        __syncthreads();
        int excl = carry + wsum[wid] + (x - v);
        if (idx < n) { g_off[idx] = excl; g_cur[idx] = excl; }
        carry += s_total;
        __syncthreads();
    }
    if (t == 0) g_off[n] = carry;
}

__global__ void scatter_kernel(const int* __restrict__ src,
                               const int* __restrict__ dst, int e) {
    int i = blockIdx.x * blockDim.x + threadIdx.x;
    if (i < e) {
        int d = dst[i];
        int p = atomicAdd(&g_cur[d], 1);
        g_ssrc[p] = src[i];
    }
}

// ---------------- aggregation: batched-LDG inner loop (MLP up), 4 blocks/SM ----------------
__global__ void __launch_bounds__(256, 4)
agg_kernel(const float* __restrict__ bias,
           float* __restrict__ outext, int use_ext,
           int apply_elu, int n) {
    __shared__ float s_wT[8][HEADS][32];   // [warp][head][edge]
    __shared__ int   s_sn[8][32];
    int wip = threadIdx.x >> 5;
    int node = blockIdx.x * 8 + wip;
    if (node >= n) return;
    int lane = threadIdx.x & 31;
    int hd = lane >> 3;
    int j0 = g_off[node], j1 = g_off[node + 1];
    float4 ald = *(const float4*)(g_ald + node * HEADS);
    float den = 0.f;
    unsigned long long acc01 = 0ULL, acc23 = 0ULL;

    const float* hwl = g_hw + lane * 4;
    const float* whd = &s_wT[wip][hd][0];
    const int*   snp = &s_sn[wip][0];

    for (int base = j0; base < j1; base += 32) {
        int j = base + lane;
        float4 w4 = make_float4(0.f, 0.f, 0.f, 0.f);
        int sn = 0;
        if (j < j1) {
            sn = g_ssrc[j];
            float4 al = *(const float4*)(g_als + sn * HEADS);
            float e0 = al.x + ald.x; e0 = fmaxf(e0, 0.2f * e0);
            float e1 = al.y + ald.y; e1 = fmaxf(e1, 0.2f * e1);
            float e2 = al.z + ald.z; e2 = fmaxf(e2, 0.2f * e2);
            float e3 = al.w + ald.w; e3 = fmaxf(e3, 0.2f * e3);
            w4.x = __expf(e0); w4.y = __expf(e1);
            w4.z = __expf(e2); w4.w = __expf(e3);
        }
        s_sn[wip][lane] = sn;
        s_wT[wip][0][lane] = w4.x;
        s_wT[wip][1][lane] = w4.y;
        s_wT[wip][2][lane] = w4.z;
        s_wT[wip][3][lane] = w4.w;
        __syncwarp();
        int cnt = min(32, j1 - base);
        int ngrp = cnt >> 2;
        #pragma unroll 2
        for (int g = 0; g < ngrp; g++) {
            int4   s4 = *(const int4*)(snp + g * 4);
            float4 wv = *(const float4*)(whd + g * 4);
            // issue all 4 gathers back-to-back (MLP), THEN consume
            float4 hv0 = *(const float4*)(hwl + (size_t)s4.x * F);
            float4 hv1 = *(const float4*)(hwl + (size_t)s4.y * F);
            float4 hv2 = *(const float4*)(hwl + (size_t)s4.z * F);
            float4 hv3 = *(const float4*)(hwl + (size_t)s4.w * F);
            den += wv.x; den += wv.y; den += wv.z; den += wv.w;
            unsigned long long w0 = dup2(wv.x), w1 = dup2(wv.y);
            unsigned long long w2 = dup2(wv.z), w3 = dup2(wv.w);
            const unsigned long long* q0 = reinterpret_cast<const unsigned long long*>(&hv0);
            const unsigned long long* q1 = reinterpret_cast<const unsigned long long*>(&hv1);
            const unsigned long long* q2 = reinterpret_cast<const unsigned long long*>(&hv2);
            const unsigned long long* q3 = reinterpret_cast<const unsigned long long*>(&hv3);
            acc01 = ffma2(w0, q0[0], acc01);
            acc23 = ffma2(w0, q0[1], acc23);
            acc01 = ffma2(w1, q1[0], acc01);
            acc23 = ffma2(w1, q1[1], acc23);
            acc01 = ffma2(w2, q2[0], acc01);
            acc23 = ffma2(w2, q2[1], acc23);
            acc01 = ffma2(w3, q3[0], acc01);
            acc23 = ffma2(w3, q3[1], acc23);
        }
        for (int jj = ngrp * 4; jj < cnt; jj++) {
            int s = snp[jj];
            float wgt = whd[jj];
            den += wgt;
            unsigned long long w2 = dup2(wgt);
            float4 hv = *(const float4*)(hwl + (size_t)s * F);
            const unsigned long long* hq = reinterpret_cast<const unsigned long long*>(&hv);
            acc01 = ffma2(w2, hq[0], acc01);
            acc23 = ffma2(w2, hq[1], acc23);
        }
        __syncwarp();
    }

    float2 a01 = *reinterpret_cast<float2*>(&acc01);
    float2 a23 = *reinterpret_cast<float2*>(&acc23);
    float inv = 1.f / (den + 1e-16f);
    float4 bv = *(const float4*)(bias + lane * 4);
    float4 o;
    o.x = fmaf(a01.x, inv, bv.x);
    o.y = fmaf(a01.y, inv, bv.y);
    o.z = fmaf(a23.x, inv, bv.z);
    o.w = fmaf(a23.y, inv, bv.w);
    if (apply_elu) {
        o.x = o.x > 0.f ? o.x : expm1f(o.x);
        o.y = o.y > 0.f ? o.y : expm1f(o.y);
        o.z = o.z > 0.f ? o.z : expm1f(o.z);
        o.w = o.w > 0.f ? o.w : expm1f(o.w);
    }
    if (use_ext) {
        *(float4*)(outext + (size_t)node * F + lane * 4) = o;
    } else {
        union { __half2 h[2]; uint2 u; } pk;
        pk.h[0] = __floats2half2_rn(o.x, o.y);
        pk.h[1] = __floats2half2_rn(o.z, o.w);
        *(uint2*)(g_feath + (size_t)node * F + lane * 4) = pk.u;
    }
}

// ---------------- launch ----------------
extern "C" void kernel_launch(void* const* d_in, const int* in_sizes, int n_in,
                              void* d_out, int out_size) {
    const float* x   = (const float*)d_in[0];
    const int*   src = (const int*)d_in[1];
    const int*   dst = (const int*)d_in[2];
    const int n = in_sizes[0] / F;
    const int e = in_sizes[1];

    const int gemm_grid = (n + 127) / 128;
    const int agg_grid  = (n + 7) / 8;

    cudaFuncSetAttribute(fused0_kernel,
                         cudaFuncAttributeMaxDynamicSharedMemorySize, GEMM_SMEM);
    cudaFuncSetAttribute(gemm128_kernel,
                         cudaFuncAttributeMaxDynamicSharedMemorySize, GEMM_SMEM);

    // 8 launches; agg0 is launch #4 -> ncu sample slot
    fused0_kernel<<<gemm_grid + HIST_BLOCKS + 2, 256, GEMM_SMEM>>>(
        x, (const float*)d_in[3], (const float*)d_in[4], (const float*)d_in[5],
        n, dst, e, (const float*)d_in[7], (const float*)d_in[11], gemm_grid);
    scan_kernel<<<1, 1024>>>(n);
    scatter_kernel<<<(e + 255) / 256, 256>>>(src, dst, e);
    agg_kernel<<<agg_grid, 256>>>((const float*)d_in[6], (float*)d_out, 0, 1, n);

    for (int l = 1; l < 3; l++) {
        const float* asrc = (const float*)d_in[4 + 4 * l];
        const float* adst = (const float*)d_in[5 + 4 * l];
        const float* b    = (const float*)d_in[6 + 4 * l];
        gemm128_kernel<<<gemm_grid, 256, GEMM_SMEM>>>(l - 1, asrc, adst, n);
        int last = (l == 2);
        agg_kernel<<<agg_grid, 256>>>(b, (float*)d_out, last, last ? 0 : 1, n);
    }
}